// round 16
// baseline (speedup 1.0000x reference)
#include <cuda_runtime.h>
#include <cuda_fp16.h>
#include <math.h>
#include <stdint.h>

#define D        1024
#define E_TOT    10
#define E_TRUE   8
#define MAX_T    8192
#define BM       128
#define BN       128
#define KT       64        // k-chunk: 64 fp16 = 128 bytes = one SW128 row
#define NKC      (D / KT)  // 16 chunks
#define STAGES   5
#define W_SCALE      1024.0f
#define W_INV_SCALE  (1.0f / 1024.0f)

// ---------------- device scratch (__device__ globals) ----------------------
__device__ int   g_cnt[E_TRUE];
__device__ int   g_tok[E_TRUE * MAX_T];
__device__ float g_wt [E_TRUE * MAX_T];
__device__ __half g_x  [MAX_T * D];        // fp16(x)
__device__ __half g_w  [E_TRUE * D * D];   // [e][n][k] transposed, x1024

// ---------------- PTX helpers (<= sm_90 baseline features only) ------------
__device__ __forceinline__ uint32_t smem_u32(const void* p) {
    uint32_t a;
    asm("{ .reg .u64 t; cvta.to.shared.u64 t, %1; cvt.u32.u64 %0, t; }"
        : "=r"(a) : "l"(p));
    return a;
}
#define SW128(off) ((off) ^ (((off) >> 3) & 0x70))

__device__ __forceinline__ void cp16(uint32_t dst, const void* src) {
    asm volatile("cp.async.cg.shared.global [%0], [%1], 16;"
                 :: "r"(dst), "l"(__cvta_generic_to_global(src)));
}
__device__ __forceinline__ void cp_commit() {
    asm volatile("cp.async.commit_group;");
}
template <int N>
__device__ __forceinline__ void cp_wait() {
    asm volatile("cp.async.wait_group %0;" :: "n"(N));
}
__device__ __forceinline__ void ldsm_x4(uint32_t* r, uint32_t addr) {
    asm volatile("ldmatrix.sync.aligned.m8n8.x4.shared.b16 {%0,%1,%2,%3}, [%4];"
                 : "=r"(r[0]), "=r"(r[1]), "=r"(r[2]), "=r"(r[3]) : "r"(addr));
}
__device__ __forceinline__ void mma16816(float* d, const uint32_t* a,
                                         uint32_t b0, uint32_t b1) {
    asm volatile(
        "mma.sync.aligned.m16n8k16.row.col.f32.f16.f16.f32 "
        "{%0,%1,%2,%3}, {%4,%5,%6,%7}, {%8,%9}, {%0,%1,%2,%3};"
        : "+f"(d[0]), "+f"(d[1]), "+f"(d[2]), "+f"(d[3])
        : "r"(a[0]), "r"(a[1]), "r"(a[2]), "r"(a[3]), "r"(b0), "r"(b1));
}

// ---------------- moe_mma SMEM layout (5-stage, BN=128) ---------------------
#define OFF_TOK  0                         // 128 ints
#define OFF_W    512                       // 128 floats
#define OFF_A    1024                      // A stages: 5 x 16KB
#define OFF_B    (1024 + STAGES*16384)     // B stages: 5 x 16KB
#define SMEM_BYTES (OFF_B + STAGES*16384)  // 164864 -> occ 1

#define GATE_BLOCKS  (MAX_T / 8)           // 1024
#define CONVW_BLOCKS 1024                  // 128k x 64n tiles

// ---------------------------------------------------------------------------
// Fused prologue (unchanged from R15): gate + convert_x + zero out rows, and
// convert_w 128x64 tiles with MLP=8 front-batched loads.
__global__ __launch_bounds__(256)
void prologue_kernel(const float* __restrict__ x,
                     const float* __restrict__ gw,
                     const float* __restrict__ gb,
                     const float* __restrict__ ew,
                     float* __restrict__ out, int T) {
    const int tid = threadIdx.x;

    if (blockIdx.x < GATE_BLOCKS) {
        int gtid = blockIdx.x * 256 + tid;
        int t = gtid >> 5;
        int lane = gtid & 31;
        if (t >= T) return;

        const float4* xr  = (const float4*)(x + (size_t)t * D);
        const float4* gw4 = (const float4*)gw;

        float4 v[8];
#pragma unroll
        for (int p = 0; p < 8; p++) v[p] = xr[p * 32 + lane];

        {
            float4 z = make_float4(0.f, 0.f, 0.f, 0.f);
            float4* orow = (float4*)(out + (size_t)t * D);
#pragma unroll
            for (int p = 0; p < 8; p++) orow[p * 32 + lane] = z;
        }

        float dot[E_TOT];
#pragma unroll
        for (int e = 0; e < E_TOT; e++) dot[e] = 0.f;

#pragma unroll
        for (int p = 0; p < 8; p++) {
            int f = p * 32 + lane;
            __half2 h01 = __floats2half2_rn(v[p].x, v[p].y);
            __half2 h23 = __floats2half2_rn(v[p].z, v[p].w);
            uint2 pk;
            pk.x = *(uint32_t*)&h01;
            pk.y = *(uint32_t*)&h23;
            *(uint2*)(g_x + (size_t)t * D + f * 4) = pk;
#pragma unroll
            for (int e = 0; e < E_TOT; e++) {
                float4 w = gw4[e * (D / 4) + f];
                dot[e] += v[p].x * w.x + v[p].y * w.y
                        + v[p].z * w.z + v[p].w * w.w;
            }
        }
#pragma unroll
        for (int e = 0; e < E_TOT; e++) {
#pragma unroll
            for (int off = 16; off; off >>= 1)
                dot[e] += __shfl_xor_sync(0xffffffffu, dot[e], off);
        }
        if (lane == 0) {
            float p[E_TOT];
            float mx = -1e30f;
#pragma unroll
            for (int e = 0; e < E_TOT; e++) { p[e] = dot[e] + gb[e]; mx = fmaxf(mx, p[e]); }
            float s = 0.f;
#pragma unroll
            for (int e = 0; e < E_TOT; e++) { p[e] = expf(p[e] - mx); s += p[e]; }
            int i1 = 0;
#pragma unroll
            for (int e = 1; e < E_TOT; e++) if (p[e] > p[i1]) i1 = e;
            int i2 = (i1 == 0) ? 1 : 0;
#pragma unroll
            for (int e = 0; e < E_TOT; e++) if (e != i1 && p[e] > p[i2]) i2 = e;

            float w1 = p[i1] / s, w2 = p[i2] / s;
            float t1 = (i1 < E_TRUE) ? w1 : 0.f;
            float t2 = (i2 < E_TRUE) ? w2 : 0.f;
            float den = t1 + t2;
            den = (den > 0.f) ? den : 1.f;
            t1 /= den; t2 /= den;
            if (i1 < E_TRUE) {
                int pos = atomicAdd(&g_cnt[i1], 1);
                g_tok[i1 * MAX_T + pos] = t;  g_wt[i1 * MAX_T + pos] = t1;
            }
            if (i2 < E_TRUE) {
                int pos = atomicAdd(&g_cnt[i2], 1);
                g_tok[i2 * MAX_T + pos] = t;  g_wt[i2 * MAX_T + pos] = t2;
            }
        }
    } else {
        __shared__ float tile[128][65];
        int idx = blockIdx.x - GATE_BLOCKS;
        const int e  = idx >> 7;
        const int k0 = ((idx >> 4) & 7) * 128;
        const int n0 = (idx & 15) * 64;
        const int seg = tid & 15;
        const int krow = tid >> 4;

        const float* src = ew + (size_t)e * D * D;
        float4 v[8];
#pragma unroll
        for (int p = 0; p < 8; p++)
            v[p] = *(const float4*)(src + (size_t)(k0 + krow + p * 16) * D
                                    + n0 + seg * 4);
#pragma unroll
        for (int p = 0; p < 8; p++) {
            int k = krow + p * 16;
            tile[k][seg * 4 + 0] = v[p].x;
            tile[k][seg * 4 + 1] = v[p].y;
            tile[k][seg * 4 + 2] = v[p].z;
            tile[k][seg * 4 + 3] = v[p].w;
        }
        __syncthreads();

        __half* dst = g_w + (size_t)e * D * D;
#pragma unroll
        for (int q = 0; q < 8; q++) {
            int flat = tid + q * 256;
            int n  = flat >> 5;
            int kk = (flat & 31) * 4;
            __half2 h01 = __floats2half2_rn(tile[kk + 0][n] * W_SCALE,
                                            tile[kk + 1][n] * W_SCALE);
            __half2 h23 = __floats2half2_rn(tile[kk + 2][n] * W_SCALE,
                                            tile[kk + 3][n] * W_SCALE);
            uint2 pk;
            pk.x = *(uint32_t*)&h01;
            pk.y = *(uint32_t*)&h23;
            *(uint2*)(dst + (size_t)(n0 + n) * D + k0 + kk) = pk;
        }
    }
}

// ---------------------------------------------------------------------------
// Grouped fp16 HMMA GEMM: CTA 128x128, warp tile 64x32, 5-stage cp.async,
// register fragment double-buffering (ldsm for ks+1 overlaps mma of ks).
// occ 1 (regs+smem); global latency covered by pipeline depth.
__global__ __launch_bounds__(256)
void moe_mma(const float* __restrict__ eb, float* __restrict__ out) {
    extern __shared__ __align__(1024) char smem[];
    const int e = blockIdx.z;
    const int rows = g_cnt[e];
    const int m0 = blockIdx.y * BM;
    if (m0 >= rows) return;
    const int n0 = blockIdx.x * BN;

    const uint32_t sb = smem_u32(smem);
    const int tid = threadIdx.x;
    const int wid = tid >> 5;
    const int lane = tid & 31;
    const int wm = (wid >> 2) * 64;
    const int wn = (wid & 3) * 32;

    int*   sTok = (int*)(smem + OFF_TOK);
    float* sW   = (float*)(smem + OFF_W);
    if (tid < BM) {
        int gr = m0 + tid;
        sTok[tid] = (gr < rows) ? g_tok[e * MAX_T + gr] : 0;
        sW[tid]   = (gr < rows) ? g_wt [e * MAX_T + gr] : 0.f;
    }
    __syncthreads();

    const __half* wsrc = g_w + (size_t)e * D * D;

    int cRow[4], cGrp[4];
    uint32_t cSw[4];
#pragma unroll
    for (int t = 0; t < 4; t++) {
        int c = tid + t * 256;
        cRow[t] = c >> 3;
        cGrp[t] = c & 7;
        cSw[t]  = SW128((uint32_t)(cRow[t] * 128 + cGrp[t] * 16));
    }

    auto loadChunk = [&](int kc, int buf) {
        const int k0 = kc * KT;
        uint32_t abase = sb + OFF_A + buf * 16384;
        uint32_t bbase = sb + OFF_B + buf * 16384;
#pragma unroll
        for (int t = 0; t < 4; t++) {
            cp16(abase + cSw[t],
                 g_x + (size_t)sTok[cRow[t]] * D + k0 + cGrp[t] * 8);
            cp16(bbase + cSw[t],
                 wsrc + (size_t)(n0 + cRow[t]) * D + k0 + cGrp[t] * 8);
        }
    };

    // pre-swizzled k-invariant ldsm offsets; per-ks address = base + (off ^ (ks<<5))
    // (valid: bits 5-6 of the unswizzled offsets are 0, swizzle source bits 7-9
    //  unaffected by ks*32, so SW128(off + ks*32) == SW128(off) ^ (ks<<5))
    uint32_t aOffS[4], bOffS[2];
#pragma unroll
    for (int i = 0; i < 4; i++)
        aOffS[i] = SW128((uint32_t)((wm + 16 * i + (lane & 15)) * 128
                                    + (lane >> 4) * 16));
#pragma unroll
    for (int jj = 0; jj < 2; jj++)
        bOffS[jj] = SW128((uint32_t)((wn + 16 * jj + ((lane >> 3) & 1) * 8
                                      + (lane & 7)) * 128 + (lane >> 4) * 16));

    float acc[4][4][4];
#pragma unroll
    for (int i = 0; i < 4; i++)
#pragma unroll
        for (int j = 0; j < 4; j++)
#pragma unroll
            for (int r = 0; r < 4; r++) acc[i][j][r] = 0.f;

    // prime STAGES-1 chunks (one commit group per chunk)
#pragma unroll
    for (int kc = 0; kc < STAGES - 1; kc++) {
        loadChunk(kc, kc);
        cp_commit();
    }

    uint32_t aF[2][4][4], bF[2][2][4];   // double-buffered fragments

    for (int kc = 0; kc < NKC; kc++) {
        const int buf = kc % STAGES;
        cp_wait<STAGES - 2>();      // chunk kc resident
        __syncthreads();            // all warps finished chunk kc-1 compute

        // keep one commit per iteration (possibly empty) so group counting holds
        if (kc + STAGES - 1 < NKC)
            loadChunk(kc + STAGES - 1, (kc + STAGES - 1) % STAGES);
        cp_commit();

        const uint32_t ab = sb + OFF_A + buf * 16384;
        const uint32_t bb = sb + OFF_B + buf * 16384;

        // load ks=0 fragments
        int cur = 0;
#pragma unroll
        for (int i = 0; i < 4; i++) ldsm_x4(aF[0][i], ab + aOffS[i]);
#pragma unroll
        for (int jj = 0; jj < 2; jj++) ldsm_x4(bF[0][jj], bb + bOffS[jj]);

#pragma unroll
        for (int ks = 0; ks < 4; ks++) {
            const int nxt = cur ^ 1;
            if (ks < 3) {   // prefetch ks+1 fragments (overlaps mma below)
                const uint32_t kx = (uint32_t)((ks + 1) << 5);
#pragma unroll
                for (int i = 0; i < 4; i++)
                    ldsm_x4(aF[nxt][i], ab + (aOffS[i] ^ kx));
#pragma unroll
                for (int jj = 0; jj < 2; jj++)
                    ldsm_x4(bF[nxt][jj], bb + (bOffS[jj] ^ kx));
            }
#pragma unroll
            for (int i = 0; i < 4; i++)
#pragma unroll
                for (int j = 0; j < 4; j++)
                    mma16816(acc[i][j], aF[cur][i],
                             bF[cur][j >> 1][j & 1], bF[cur][j >> 1][(j & 1) + 2]);
            cur = nxt;
        }
    }

    // Epilogue: undo W_SCALE, add bias, apply gate weight, scatter-atomic.
    const int tig = lane & 3;
    const int grp = lane >> 2;
    const float* brow = eb + e * D + n0 + wn;
#pragma unroll
    for (int i = 0; i < 4; i++) {
#pragma unroll
        for (int h = 0; h < 2; h++) {
            int r = wm + 16 * i + grp + h * 8;
            int gr = m0 + r;
            if (gr < rows) {
                int tok = sTok[r];
                float w = sW[r];
                float* orow = out + (size_t)tok * D + n0 + wn;
#pragma unroll
                for (int j = 0; j < 4; j++) {
                    int col = 8 * j + 2 * tig;
                    float y0 = acc[i][j][h * 2 + 0] * W_INV_SCALE;
                    float y1 = acc[i][j][h * 2 + 1] * W_INV_SCALE;
                    atomicAdd(&orow[col],     w * (y0 + brow[col]));
                    atomicAdd(&orow[col + 1], w * (y1 + brow[col + 1]));
                }
            }
        }
    }
}

// ---------------------------------------------------------------------------
extern "C" void kernel_launch(void* const* d_in, const int* in_sizes, int n_in,
                              void* d_out, int out_size) {
    const float* x  = (const float*)d_in[0];
    const float* gw = (const float*)d_in[1];
    const float* gb = (const float*)d_in[2];
    const float* ew = (const float*)d_in[3];
    const float* eb = (const float*)d_in[4];
    float* out = (float*)d_out;

    const int T = in_sizes[0] / D;

    static void* cnt_addr = nullptr;
    if (!cnt_addr) {
        cudaGetSymbolAddress(&cnt_addr, g_cnt);
        cudaFuncSetAttribute(moe_mma,
                             cudaFuncAttributeMaxDynamicSharedMemorySize,
                             SMEM_BYTES);
    }

    cudaMemsetAsync(cnt_addr, 0, E_TRUE * sizeof(int), 0);

    {   // fused: gate + convert_x + zero-out + convert_w
        prologue_kernel<<<GATE_BLOCKS + CONVW_BLOCKS, 256>>>(x, gw, gb, ew,
                                                             out, T);
    }
    {   // grouped HMMA GEMM (5-stage, frag double-buffered)
        dim3 grid(D / BN, (T + BM - 1) / BM, E_TRUE);
        moe_mma<<<grid, 256, SMEM_BYTES>>>(eb, out);
    }
}

// round 17
// speedup vs baseline: 1.1881x; 1.1881x over previous
#include <cuda_runtime.h>
#include <cuda_fp16.h>
#include <math.h>
#include <stdint.h>

#define D        1024
#define E_TOT    10
#define E_TRUE   8
#define MAX_T    8192
#define BM       128
#define BN       128
#define KT       64        // k-chunk: 64 fp16 = 128 bytes = one SW128 row
#define NKC      (D / KT)  // 16 chunks
#define STAGES   3
#define W_SCALE      1024.0f
#define W_INV_SCALE  (1.0f / 1024.0f)

// ---------------- device scratch (__device__ globals) ----------------------
__device__ int   g_cnt[E_TRUE];
__device__ int   g_tok[E_TRUE * MAX_T];
__device__ float g_wt [E_TRUE * MAX_T];
__device__ __half g_x  [MAX_T * D];        // fp16(x)
__device__ __half g_w  [E_TRUE * D * D];   // [e][n][k] transposed, x1024

// ---------------- PTX helpers (<= sm_90 baseline features only) ------------
__device__ __forceinline__ uint32_t smem_u32(const void* p) {
    uint32_t a;
    asm("{ .reg .u64 t; cvta.to.shared.u64 t, %1; cvt.u32.u64 %0, t; }"
        : "=r"(a) : "l"(p));
    return a;
}
#define SW128(off) ((off) ^ (((off) >> 3) & 0x70))

__device__ __forceinline__ void cp16(uint32_t dst, const void* src) {
    asm volatile("cp.async.cg.shared.global [%0], [%1], 16;"
                 :: "r"(dst), "l"(__cvta_generic_to_global(src)));
}
__device__ __forceinline__ void cp_commit() {
    asm volatile("cp.async.commit_group;");
}
template <int N>
__device__ __forceinline__ void cp_wait() {
    asm volatile("cp.async.wait_group %0;" :: "n"(N));
}
__device__ __forceinline__ void ldsm_x4(uint32_t* r, uint32_t addr) {
    asm volatile("ldmatrix.sync.aligned.m8n8.x4.shared.b16 {%0,%1,%2,%3}, [%4];"
                 : "=r"(r[0]), "=r"(r[1]), "=r"(r[2]), "=r"(r[3]) : "r"(addr));
}
__device__ __forceinline__ void mma16816(float* d, const uint32_t* a,
                                         uint32_t b0, uint32_t b1) {
    asm volatile(
        "mma.sync.aligned.m16n8k16.row.col.f32.f16.f16.f32 "
        "{%0,%1,%2,%3}, {%4,%5,%6,%7}, {%8,%9}, {%0,%1,%2,%3};"
        : "+f"(d[0]), "+f"(d[1]), "+f"(d[2]), "+f"(d[3])
        : "r"(a[0]), "r"(a[1]), "r"(a[2]), "r"(a[3]), "r"(b0), "r"(b1));
}

// ---------------- moe_mma SMEM layout (3-stage, BN=128) ---------------------
#define OFF_TOK  0                        // 128 ints
#define OFF_W    512                      // 128 floats
#define OFF_A    1024                     // A stages: 3 x 16KB
#define OFF_B    (1024 + STAGES*16384)    // B stages: 3 x 16KB
#define SMEM_BYTES (OFF_B + STAGES*16384) // 99328 -> 2 CTAs/SM

#define GATE_BLOCKS  (MAX_T / 8)          // 1024
#define CONVW_BLOCKS 1024                 // 128k x 64n tiles

// ---------------------------------------------------------------------------
// Fused prologue: gate + convert_x + zero out rows (blocks < GATE_BLOCKS),
// convert_w 128x64 tiles with MLP=8 front-batched loads (the rest).
__global__ __launch_bounds__(256)
void prologue_kernel(const float* __restrict__ x,
                     const float* __restrict__ gw,
                     const float* __restrict__ gb,
                     const float* __restrict__ ew,
                     float* __restrict__ out, int T) {
    const int tid = threadIdx.x;

    if (blockIdx.x < GATE_BLOCKS) {
        int gtid = blockIdx.x * 256 + tid;
        int t = gtid >> 5;
        int lane = gtid & 31;
        if (t >= T) return;

        const float4* xr  = (const float4*)(x + (size_t)t * D);
        const float4* gw4 = (const float4*)gw;

        float4 v[8];
#pragma unroll
        for (int p = 0; p < 8; p++) v[p] = xr[p * 32 + lane];

        {
            float4 z = make_float4(0.f, 0.f, 0.f, 0.f);
            float4* orow = (float4*)(out + (size_t)t * D);
#pragma unroll
            for (int p = 0; p < 8; p++) orow[p * 32 + lane] = z;
        }

        float dot[E_TOT];
#pragma unroll
        for (int e = 0; e < E_TOT; e++) dot[e] = 0.f;

#pragma unroll
        for (int p = 0; p < 8; p++) {
            int f = p * 32 + lane;
            __half2 h01 = __floats2half2_rn(v[p].x, v[p].y);
            __half2 h23 = __floats2half2_rn(v[p].z, v[p].w);
            uint2 pk;
            pk.x = *(uint32_t*)&h01;
            pk.y = *(uint32_t*)&h23;
            *(uint2*)(g_x + (size_t)t * D + f * 4) = pk;
#pragma unroll
            for (int e = 0; e < E_TOT; e++) {
                float4 w = gw4[e * (D / 4) + f];
                dot[e] += v[p].x * w.x + v[p].y * w.y
                        + v[p].z * w.z + v[p].w * w.w;
            }
        }
#pragma unroll
        for (int e = 0; e < E_TOT; e++) {
#pragma unroll
            for (int off = 16; off; off >>= 1)
                dot[e] += __shfl_xor_sync(0xffffffffu, dot[e], off);
        }
        if (lane == 0) {
            float p[E_TOT];
            float mx = -1e30f;
#pragma unroll
            for (int e = 0; e < E_TOT; e++) { p[e] = dot[e] + gb[e]; mx = fmaxf(mx, p[e]); }
            float s = 0.f;
#pragma unroll
            for (int e = 0; e < E_TOT; e++) { p[e] = expf(p[e] - mx); s += p[e]; }
            int i1 = 0;
#pragma unroll
            for (int e = 1; e < E_TOT; e++) if (p[e] > p[i1]) i1 = e;
            int i2 = (i1 == 0) ? 1 : 0;
#pragma unroll
            for (int e = 0; e < E_TOT; e++) if (e != i1 && p[e] > p[i2]) i2 = e;

            float w1 = p[i1] / s, w2 = p[i2] / s;
            float t1 = (i1 < E_TRUE) ? w1 : 0.f;
            float t2 = (i2 < E_TRUE) ? w2 : 0.f;
            float den = t1 + t2;
            den = (den > 0.f) ? den : 1.f;
            t1 /= den; t2 /= den;
            if (i1 < E_TRUE) {
                int pos = atomicAdd(&g_cnt[i1], 1);
                g_tok[i1 * MAX_T + pos] = t;  g_wt[i1 * MAX_T + pos] = t1;
            }
            if (i2 < E_TRUE) {
                int pos = atomicAdd(&g_cnt[i2], 1);
                g_tok[i2 * MAX_T + pos] = t;  g_wt[i2 * MAX_T + pos] = t2;
            }
        }
    } else {
        __shared__ float tile[128][65];
        int idx = blockIdx.x - GATE_BLOCKS;
        const int e  = idx >> 7;
        const int k0 = ((idx >> 4) & 7) * 128;
        const int n0 = (idx & 15) * 64;
        const int seg = tid & 15;
        const int krow = tid >> 4;

        const float* src = ew + (size_t)e * D * D;
        float4 v[8];
#pragma unroll
        for (int p = 0; p < 8; p++)
            v[p] = *(const float4*)(src + (size_t)(k0 + krow + p * 16) * D
                                    + n0 + seg * 4);
#pragma unroll
        for (int p = 0; p < 8; p++) {
            int k = krow + p * 16;
            tile[k][seg * 4 + 0] = v[p].x;
            tile[k][seg * 4 + 1] = v[p].y;
            tile[k][seg * 4 + 2] = v[p].z;
            tile[k][seg * 4 + 3] = v[p].w;
        }
        __syncthreads();

        __half* dst = g_w + (size_t)e * D * D;
#pragma unroll
        for (int q = 0; q < 8; q++) {
            int flat = tid + q * 256;
            int n  = flat >> 5;
            int kk = (flat & 31) * 4;
            __half2 h01 = __floats2half2_rn(tile[kk + 0][n] * W_SCALE,
                                            tile[kk + 1][n] * W_SCALE);
            __half2 h23 = __floats2half2_rn(tile[kk + 2][n] * W_SCALE,
                                            tile[kk + 3][n] * W_SCALE);
            uint2 pk;
            pk.x = *(uint32_t*)&h01;
            pk.y = *(uint32_t*)&h23;
            *(uint2*)(dst + (size_t)(n0 + n) * D + k0 + kk) = pk;
        }
    }
}

// ---------------------------------------------------------------------------
// Grouped fp16 HMMA GEMM — R14 structure (3-stage, occ 2, warp 64x32) with
// pre-swizzled ldsm bases: addr = base ^ (ks<<5) (1 XOR on the critical path
// instead of shift+and+xor+add per ldsm).
__global__ __launch_bounds__(256, 2)
void moe_mma(const float* __restrict__ eb, float* __restrict__ out) {
    extern __shared__ __align__(1024) char smem[];
    const int e = blockIdx.z;
    const int rows = g_cnt[e];
    const int m0 = blockIdx.y * BM;
    if (m0 >= rows) return;
    const int n0 = blockIdx.x * BN;

    const uint32_t sb = smem_u32(smem);
    const int tid = threadIdx.x;
    const int wid = tid >> 5;
    const int lane = tid & 31;
    const int wm = (wid >> 2) * 64;
    const int wn = (wid & 3) * 32;

    int*   sTok = (int*)(smem + OFF_TOK);
    float* sW   = (float*)(smem + OFF_W);
    if (tid < BM) {
        int gr = m0 + tid;
        sTok[tid] = (gr < rows) ? g_tok[e * MAX_T + gr] : 0;
        sW[tid]   = (gr < rows) ? g_wt [e * MAX_T + gr] : 0.f;
    }
    __syncthreads();

    const __half* wsrc = g_w + (size_t)e * D * D;

    int cRow[4], cGrp[4];
    uint32_t cSw[4];
#pragma unroll
    for (int t = 0; t < 4; t++) {
        int c = tid + t * 256;
        cRow[t] = c >> 3;
        cGrp[t] = c & 7;
        cSw[t]  = SW128((uint32_t)(cRow[t] * 128 + cGrp[t] * 16));
    }

    auto loadChunk = [&](int kc, int buf) {
        const int k0 = kc * KT;
        uint32_t abase = sb + OFF_A + buf * 16384;
        uint32_t bbase = sb + OFF_B + buf * 16384;
#pragma unroll
        for (int t = 0; t < 4; t++) {
            cp16(abase + cSw[t],
                 g_x + (size_t)sTok[cRow[t]] * D + k0 + cGrp[t] * 8);
            cp16(bbase + cSw[t],
                 wsrc + (size_t)(n0 + cRow[t]) * D + k0 + cGrp[t] * 8);
        }
        cp_commit();
    };

    // pre-swizzled k-invariant ldsm addresses (SMEM-absolute, per stage added
    // later). SW128(off + ks*32) == SW128(off) ^ (ks<<5): bits 5-6 of off are
    // zero and ks*32 never carries into the swizzle source bits [7:9].
    uint32_t aOffS[4], bOffS[2];
#pragma unroll
    for (int i = 0; i < 4; i++)
        aOffS[i] = SW128((uint32_t)((wm + 16 * i + (lane & 15)) * 128
                                    + (lane >> 4) * 16));
#pragma unroll
    for (int jj = 0; jj < 2; jj++)
        bOffS[jj] = SW128((uint32_t)((wn + 16 * jj + ((lane >> 3) & 1) * 8
                                      + (lane & 7)) * 128 + (lane >> 4) * 16));

    float acc[4][4][4];
#pragma unroll
    for (int i = 0; i < 4; i++)
#pragma unroll
        for (int j = 0; j < 4; j++)
#pragma unroll
            for (int r = 0; r < 4; r++) acc[i][j][r] = 0.f;

    loadChunk(0, 0);
    loadChunk(1, 1);

    for (int kc = 0; kc < NKC; kc++) {
        const int buf = kc % STAGES;
        cp_wait<STAGES - 2>();
        __syncthreads();

        if (kc + STAGES - 1 < NKC)
            loadChunk(kc + STAGES - 1, (kc + STAGES - 1) % STAGES);

        const uint32_t ab = sb + OFF_A + buf * 16384;
        const uint32_t bb = sb + OFF_B + buf * 16384;

#pragma unroll
        for (int ks = 0; ks < 4; ks++) {
            const uint32_t kx = (uint32_t)(ks << 5);
            uint32_t b[2][4];
#pragma unroll
            for (int jj = 0; jj < 2; jj++)
                ldsm_x4(b[jj], bb + (bOffS[jj] ^ kx));
            uint32_t a[4][4];
#pragma unroll
            for (int i = 0; i < 4; i++)
                ldsm_x4(a[i], ab + (aOffS[i] ^ kx));
#pragma unroll
            for (int i = 0; i < 4; i++)
#pragma unroll
                for (int j = 0; j < 4; j++)
                    mma16816(acc[i][j], a[i],
                             b[j >> 1][j & 1], b[j >> 1][(j & 1) + 2]);
        }
    }

    // Epilogue: undo W_SCALE, add bias, apply gate weight, scatter-atomic.
    const int tig = lane & 3;
    const int grp = lane >> 2;
    const float* brow = eb + e * D + n0 + wn;
#pragma unroll
    for (int i = 0; i < 4; i++) {
#pragma unroll
        for (int h = 0; h < 2; h++) {
            int r = wm + 16 * i + grp + h * 8;
            int gr = m0 + r;
            if (gr < rows) {
                int tok = sTok[r];
                float w = sW[r];
                float* orow = out + (size_t)tok * D + n0 + wn;
#pragma unroll
                for (int j = 0; j < 4; j++) {
                    int col = 8 * j + 2 * tig;
                    float y0 = acc[i][j][h * 2 + 0] * W_INV_SCALE;
                    float y1 = acc[i][j][h * 2 + 1] * W_INV_SCALE;
                    atomicAdd(&orow[col],     w * (y0 + brow[col]));
                    atomicAdd(&orow[col + 1], w * (y1 + brow[col + 1]));
                }
            }
        }
    }
}

// ---------------------------------------------------------------------------
extern "C" void kernel_launch(void* const* d_in, const int* in_sizes, int n_in,
                              void* d_out, int out_size) {
    const float* x  = (const float*)d_in[0];
    const float* gw = (const float*)d_in[1];
    const float* gb = (const float*)d_in[2];
    const float* ew = (const float*)d_in[3];
    const float* eb = (const float*)d_in[4];
    float* out = (float*)d_out;

    const int T = in_sizes[0] / D;

    static void* cnt_addr = nullptr;
    if (!cnt_addr) {
        cudaGetSymbolAddress(&cnt_addr, g_cnt);
        cudaFuncSetAttribute(moe_mma,
                             cudaFuncAttributeMaxDynamicSharedMemorySize,
                             SMEM_BYTES);
    }

    // zero routing counters (tiny memset node; precedes gate atomics)
    cudaMemsetAsync(cnt_addr, 0, E_TRUE * sizeof(int), 0);

    {   // fused: gate + convert_x + zero-out + convert_w
        prologue_kernel<<<GATE_BLOCKS + CONVW_BLOCKS, 256>>>(x, gw, gb, ew,
                                                             out, T);
    }
    {   // grouped HMMA GEMM (R14 config + folded swizzle)
        dim3 grid(D / BN, (T + BM - 1) / BM, E_TRUE);
        moe_mma<<<grid, 256, SMEM_BYTES>>>(eb, out);
    }
}